// round 10
// baseline (speedup 1.0000x reference)
#include <cuda_runtime.h>
#include <cuda_bf16.h>
#include <cstdint>

#define D_DIM   512
#define N_HEADS 64
#define NJ      128
#define MT      128                 // M tile per CTA
#define KC      64                  // K chunk per split (64 bf16 = 128B rows)
#define NCHUNK  (D_DIM / KC)        // 8

#define TILE_SZ   16384             // 128 rows * 128B
#define STAGE_SZ  (6 * TILE_SZ)     // 3 A splits + 3 B splits = 96KB
#define SMEM_DYN  (2 * STAGE_SZ)    // 192KB

// ---- global scratch (no cudaMalloc allowed) ----
__device__ float         g_bias[NJ];
__device__ __nv_bfloat16 g_Bs[3][NJ * D_DIM];   // [split][j][k], k-contiguous
__device__ float         g_partials[512];

// ===========================================================================
// helpers
// ===========================================================================
__device__ __forceinline__ uint32_t smem_u32(const void* p) {
    uint32_t a;
    asm("{ .reg .u64 t; cvta.to.shared.u64 t, %1; cvt.u32.u64 %0, t; }" : "=r"(a) : "l"(p));
    return a;
}
__device__ __forceinline__ void cp_async16(uint32_t dst, const void* src) {
    asm volatile("cp.async.cg.shared.global [%0], [%1], 16;" :: "r"(dst), "l"(src) : "memory");
}
__device__ __forceinline__ void cp_commit() {
    asm volatile("cp.async.commit_group;" ::: "memory");
}
__device__ __forceinline__ void cp_wait0() {
    asm volatile("cp.async.wait_group 0;" ::: "memory");
}
__device__ __forceinline__ void ldmx4(uint32_t* r, uint32_t addr) {
    asm volatile("ldmatrix.sync.aligned.m8n8.x4.shared.b16 {%0,%1,%2,%3}, [%4];"
                 : "=r"(r[0]), "=r"(r[1]), "=r"(r[2]), "=r"(r[3]) : "r"(addr));
}
__device__ __forceinline__ void mma16816(float* d, const uint32_t* a, uint32_t b0, uint32_t b1) {
    asm volatile("mma.sync.aligned.m16n8k16.row.col.f32.bf16.bf16.f32 "
                 "{%0,%1,%2,%3}, {%4,%5,%6,%7}, {%8,%9}, {%0,%1,%2,%3};"
                 : "+f"(d[0]), "+f"(d[1]), "+f"(d[2]), "+f"(d[3])
                 : "r"(a[0]), "r"(a[1]), "r"(a[2]), "r"(a[3]), "r"(b0), "r"(b1));
}
__device__ __forceinline__ uint32_t pk(__nv_bfloat16 a, __nv_bfloat16 b) {
    uint16_t ua = *(uint16_t*)&a, ub = *(uint16_t*)&b;
    return (uint32_t)ua | ((uint32_t)ub << 16);
}

// ===========================================================================
// Phase 1: spectral norm per head; write bias + 3-way bf16 splits of Wt/sigma
// ===========================================================================
__global__ void prep_kernel(const float* __restrict__ W,
                            const float* __restrict__ bias_in,
                            const float* __restrict__ u) {
    int n = blockIdx.x;
    int t = threadIdx.x;
    __shared__ float r0s[128];
    __shared__ float r1s[128];

    if (t == 0) {
        g_bias[2 * n]     = bias_in[2 * n];
        g_bias[2 * n + 1] = bias_in[2 * n + 1];
    }

    const float* Wn = W + (size_t)n * 2 * D_DIM;
    float u0 = u[2 * n], u1 = u[2 * n + 1];

    float w0[4], w1[4], vr[4];
    float s = 0.f;
#pragma unroll
    for (int i = 0; i < 4; i++) {
        int d = t + i * 128;
        w0[i] = Wn[d];
        w1[i] = Wn[D_DIM + d];
        vr[i] = w0[i] * u0 + w1[i] * u1;
        s += vr[i] * vr[i];
    }
    r0s[t] = s;
    __syncthreads();
    for (int off = 64; off > 0; off >>= 1) {
        if (t < off) r0s[t] += r0s[t + off];
        __syncthreads();
    }
    float rn = 1.0f / fmaxf(sqrtf(r0s[0]), 1e-12f);
    __syncthreads();

    float t0 = 0.f, t1 = 0.f;
#pragma unroll
    for (int i = 0; i < 4; i++) {
        float v = vr[i] * rn;
        t0 += w0[i] * v;
        t1 += w1[i] * v;
    }
    r0s[t] = t0; r1s[t] = t1;
    __syncthreads();
    for (int off = 64; off > 0; off >>= 1) {
        if (t < off) { r0s[t] += r0s[t + off]; r1s[t] += r1s[t + off]; }
        __syncthreads();
    }
    float T0 = r0s[0], T1 = r1s[0];
    float den = fmaxf(sqrtf(T0 * T0 + T1 * T1), 1e-12f);
    float sigma = (T0 / den) * T0 + (T1 / den) * T1;
    float inv = 1.0f / sigma;

#pragma unroll
    for (int i = 0; i < 4; i++) {
        int d = t + i * 128;
#pragma unroll
        for (int c = 0; c < 2; c++) {
            float v = (c ? w1[i] : w0[i]) * inv;
            int j = 2 * n + c;
            __nv_bfloat16 h = __float2bfloat16_rn(v);
            float r1v = v - __bfloat162float(h);
            __nv_bfloat16 m = __float2bfloat16_rn(r1v);
            float r2v = r1v - __bfloat162float(m);
            __nv_bfloat16 l = __float2bfloat16_rn(r2v);
            g_Bs[0][(size_t)j * D_DIM + d] = h;
            g_Bs[1][(size_t)j * D_DIM + d] = m;
            g_Bs[2][(size_t)j * D_DIM + d] = l;
        }
    }
}

// ===========================================================================
// Phase 2: HMMA bf16x6 GEMM (fp32-accurate) + fused epilogue
// grid = B/128, block = 256 (8 warps, 4x2 warp grid, warp tile m32 x n64)
// ===========================================================================
__device__ __forceinline__ void conv_store_A(char* stage, int i, float4 v) {
    int row = i >> 4;
    int q = i & 15;
    float e[4] = {v.x, v.y, v.z, v.w};
    __nv_bfloat16 h[4], m[4], l[4];
#pragma unroll
    for (int k = 0; k < 4; k++) {
        h[k] = __float2bfloat16_rn(e[k]);
        float r1 = e[k] - __bfloat162float(h[k]);
        m[k] = __float2bfloat16_rn(r1);
        float r2 = r1 - __bfloat162float(m[k]);
        l[k] = __float2bfloat16_rn(r2);
    }
    uint32_t off = (uint32_t)(row * 128) + (((uint32_t)(q * 8)) ^ ((row & 7) << 4));
    *(uint2*)(stage + off)               = make_uint2(pk(h[0], h[1]), pk(h[2], h[3]));
    *(uint2*)(stage + TILE_SZ + off)     = make_uint2(pk(m[0], m[1]), pk(m[2], m[3]));
    *(uint2*)(stage + 2 * TILE_SZ + off) = make_uint2(pk(l[0], l[1]), pk(l[2], l[3]));
}

__global__ __launch_bounds__(256, 1)
void main_kernel(const float* __restrict__ A,
                 const int* __restrict__ target,
                 float* __restrict__ pred_out,
                 float* __restrict__ arg_out) {
    extern __shared__ char dsm[];
    __shared__ float s_bias[NJ];
    __shared__ float s_lred[MT];

    int tid = threadIdx.x;
    int wid = tid >> 5;
    int lane = tid & 31;
    int row0 = blockIdx.x * MT;

    uint32_t sbase = smem_u32(dsm);
    if (tid < NJ) s_bias[tid] = g_bias[tid];

    int warpM = (wid & 3) * 32;
    int warpN = (wid >> 2) * 64;

    // per-lane ldmatrix row offsets (relative to tile base) + swizzle xor
    uint32_t aOff[2], aX[2], bOff[4], bX[4];
#pragma unroll
    for (int mi = 0; mi < 2; mi++) {
        int r = warpM + mi * 16 + (lane & 15);
        aOff[mi] = (uint32_t)(r * 128);
        aX[mi]   = (uint32_t)((r & 7) << 4);
    }
#pragma unroll
    for (int nj = 0; nj < 4; nj++) {
        int r = warpN + nj * 16 + (lane & 15);
        bOff[nj] = (uint32_t)(r * 128);
        bX[nj]   = (uint32_t)((r & 7) << 4);
    }

    float acc[2][8][4];
#pragma unroll
    for (int mi = 0; mi < 2; mi++)
#pragma unroll
        for (int ni = 0; ni < 8; ni++)
#pragma unroll
            for (int k = 0; k < 4; k++) acc[mi][ni][k] = 0.f;

    const int pa[6] = {0, 0, 1, 0, 2, 1};
    const int pb[6] = {0, 1, 0, 2, 0, 1};
    const float* Abase = A + (size_t)row0 * D_DIM;

    // ---- prologue: fill stage 0 (chunk 0) ----
    {
#pragma unroll
        for (int t = 0; t < 12; t++) {          // B via cp.async
            int i = tid + t * 256;
            int sp = i >> 10;
            int r = (i >> 3) & 127;
            int q = i & 7;
            uint32_t dst = sbase + (uint32_t)((3 + sp) * TILE_SZ)
                         + (uint32_t)(r * 128) + (((uint32_t)(q * 16)) ^ ((r & 7) << 4));
            cp_async16(dst, &g_Bs[sp][(size_t)r * D_DIM + q * 8]);
        }
        cp_commit();
#pragma unroll
        for (int t = 0; t < 8; t++) {           // A: load + split + store
            int i = tid + t * 256;
            float4 v = *(const float4*)&Abase[(size_t)(i >> 4) * D_DIM + (i & 15) * 4];
            conv_store_A(dsm, i, v);
        }
        cp_wait0();
        __syncthreads();
    }

    float4 av[8];

    for (int c = 0; c < NCHUNK; c++) {
        int st = c & 1;
        char* nxt = dsm + (st ^ 1) * STAGE_SZ;

        if (c < NCHUNK - 1) {
            // kick B cp.async for chunk c+1 into the other stage
#pragma unroll
            for (int t = 0; t < 12; t++) {
                int i = tid + t * 256;
                int sp = i >> 10;
                int r = (i >> 3) & 127;
                int q = i & 7;
                uint32_t dst = sbase + (uint32_t)((st ^ 1) * STAGE_SZ + (3 + sp) * TILE_SZ)
                             + (uint32_t)(r * 128) + (((uint32_t)(q * 16)) ^ ((r & 7) << 4));
                cp_async16(dst, &g_Bs[sp][(size_t)r * D_DIM + (c + 1) * KC + q * 8]);
            }
            cp_commit();
            // prefetch A for chunk c+1 into registers (latency hidden by compute)
#pragma unroll
            for (int t = 0; t < 8; t++) {
                int i = tid + t * 256;
                av[t] = *(const float4*)&Abase[(size_t)(i >> 4) * D_DIM + (c + 1) * KC + (i & 15) * 4];
            }
        }

        // ---- compute chunk c: 6 products x 4 k16-steps ----
        uint32_t tb = sbase + (uint32_t)(st * STAGE_SZ);
#pragma unroll
        for (int p = 0; p < 6; p++) {
            uint32_t Ab = tb + (uint32_t)(pa[p] * TILE_SZ);
            uint32_t Bb = tb + (uint32_t)((3 + pb[p]) * TILE_SZ);
#pragma unroll
            for (int s = 0; s < 4; s++) {
                uint32_t kb = (uint32_t)(s * 32) + (uint32_t)(lane & 16);
                uint32_t af[2][4], bf[4][4];
                ldmx4(af[0], Ab + aOff[0] + (kb ^ aX[0]));
                ldmx4(af[1], Ab + aOff[1] + (kb ^ aX[1]));
#pragma unroll
                for (int nj = 0; nj < 4; nj++)
                    ldmx4(bf[nj], Bb + bOff[nj] + (kb ^ bX[nj]));
#pragma unroll
                for (int mi = 0; mi < 2; mi++)
#pragma unroll
                    for (int ni = 0; ni < 8; ni++) {
                        int g = ni >> 1;
                        uint32_t b0 = (ni & 1) ? bf[g][1] : bf[g][0];
                        uint32_t b1 = (ni & 1) ? bf[g][3] : bf[g][2];
                        mma16816(acc[mi][ni], af[mi], b0, b1);
                    }
            }
        }

        if (c < NCHUNK - 1) {
#pragma unroll
            for (int t = 0; t < 8; t++) conv_store_A(nxt, tid + t * 256, av[t]);
            cp_wait0();
        }
        __syncthreads();
    }

    // ---------------- epilogue ----------------
    // accums + bias -> padded smem tile (stride 132 floats)
    float* sp0 = (float*)dsm;
#pragma unroll
    for (int mi = 0; mi < 2; mi++)
#pragma unroll
        for (int ni = 0; ni < 8; ni++) {
            int r = warpM + mi * 16 + (lane >> 2);
            int cc = warpN + ni * 8 + (lane & 3) * 2;
            sp0[r * 132 + cc]           = acc[mi][ni][0] + s_bias[cc];
            sp0[r * 132 + cc + 1]       = acc[mi][ni][1] + s_bias[cc + 1];
            sp0[(r + 8) * 132 + cc]     = acc[mi][ni][2] + s_bias[cc];
            sp0[(r + 8) * 132 + cc + 1] = acc[mi][ni][3] + s_bias[cc + 1];
        }
    __syncthreads();

    // pred: coalesced copy
    if (pred_out) {
#pragma unroll
        for (int t = 0; t < 16; t++) {
            int i = tid + t * 256;
            int r = i >> 5, q = i & 31;
            float4 v = *(const float4*)&sp0[r * 132 + q * 4];
            *(float4*)&pred_out[(size_t)(row0 + r) * NJ + q * 4] = v;
        }
    }
    // argmax: coalesced
    if (arg_out) {
#pragma unroll
        for (int t = 0; t < 8; t++) {
            int i = tid + t * 256;
            int r = i >> 4, g = i & 15;
            float4 v0 = *(const float4*)&sp0[r * 132 + g * 8];
            float4 v1 = *(const float4*)&sp0[r * 132 + g * 8 + 4];
            *(float4*)&arg_out[(size_t)(row0 + r) * N_HEADS + g * 4] =
                make_float4(v0.y > v0.x ? 1.f : 0.f, v0.w > v0.z ? 1.f : 0.f,
                            v1.y > v1.x ? 1.f : 0.f, v1.w > v1.z ? 1.f : 0.f);
        }
    }
    // loss: one thread per row
    if (tid < MT) {
        int grow = row0 + tid;
        const float* rowp = &sp0[tid * 132];
        float m0 = -1e30f, m1 = -1e30f;
#pragma unroll 16
        for (int h = 0; h < N_HEADS; h++) {
            m0 = fmaxf(m0, rowp[2 * h]);
            m1 = fmaxf(m1, rowp[2 * h + 1]);
        }
        float s0 = 0.f, s1 = 0.f, tsum = 0.f, cntf = 0.f;
#pragma unroll 4
        for (int g = 0; g < 16; g++) {
            int4 t4 = *(const int4*)&target[(size_t)grow * N_HEADS + g * 4];
            int tg[4] = {t4.x, t4.y, t4.z, t4.w};
#pragma unroll
            for (int k = 0; k < 4; k++) {
                int h = g * 4 + k;
                float c0 = rowp[2 * h], c1 = rowp[2 * h + 1];
                s0 += __expf(c0 - m0);
                s1 += __expf(c1 - m1);
                tsum += tg[k] ? c1 : c0;
                cntf += (float)tg[k];
            }
        }
        float lse0 = m0 + __logf(s0);
        float lse1 = m1 + __logf(s1);
        s_lred[tid] = ((float)N_HEADS - cntf) * lse0 + cntf * lse1 - tsum;
    }
    __syncthreads();
    if (tid == 0) {
        float s = 0.f;
#pragma unroll 8
        for (int k = 0; k < MT; k++) s += s_lred[k];
        g_partials[blockIdx.x] = s;
    }
}

// ===========================================================================
// Phase 3: deterministic loss reduction
// ===========================================================================
__global__ void finish_kernel(float* __restrict__ out_loss, int nB, int B) {
    __shared__ double sm[256];
    int t = threadIdx.x;
    double v = 0.0;
    for (int i = t; i < nB; i += 256) v += (double)g_partials[i];
    sm[t] = v;
    __syncthreads();
    for (int off = 128; off; off >>= 1) {
        if (t < off) sm[t] += sm[t + off];
        __syncthreads();
    }
    if (t == 0) *out_loss = (float)(sm[0] / (2.0 * (double)B));
}

// ===========================================================================
extern "C" void kernel_launch(void* const* d_in, const int* in_sizes, int n_in,
                              void* d_out, int out_size) {
    const float* feature = (const float*)d_in[0];
    const int*   target  = (const int*)d_in[1];
    const float* W       = (const float*)d_in[2];
    const float* b       = (const float*)d_in[3];
    const float* u       = (const float*)d_in[4];

    int B = in_sizes[0] / D_DIM;  // 65536

    long long predN = (long long)B * NJ;
    long long BN    = (long long)B * N_HEADS;

    float* out = (float*)d_out;
    float* pred_out = nullptr;
    float* arg_out  = nullptr;
    long long off_loss = -1;

    if ((long long)out_size == predN + BN + 1) {
        pred_out = out; arg_out = out + predN; off_loss = predN + BN;
    } else if ((long long)out_size == predN) {
        pred_out = out;
    } else if ((long long)out_size == BN) {
        arg_out = out;
    } else if (out_size == 1) {
        off_loss = 0;
    } else {
        pred_out = out;
        if ((long long)out_size >= predN + BN)     arg_out  = out + predN;
        if ((long long)out_size >= predN + BN + 1) off_loss = predN + BN;
    }

    cudaFuncSetAttribute(main_kernel, cudaFuncAttributeMaxDynamicSharedMemorySize, SMEM_DYN);

    prep_kernel<<<N_HEADS, 128>>>(W, b, u);

    int nB = B / MT;  // 512
    main_kernel<<<nB, 256, SMEM_DYN>>>(feature, target, pred_out, arg_out);

    if (off_loss >= 0) finish_kernel<<<1, 256>>>(out + off_loss, nB, B);
}